// round 11
// baseline (speedup 1.0000x reference)
#include <cuda_runtime.h>
#include <cuda_fp16.h>
#include <cstdint>

#define N_NODES 512
#define HD      128
#define FD      192
#define MD      256
#define JT      8
#define TJ      64
#define SA_STRH 264      // sA row stride in halves (132 words == 4 mod 32 -> conflict-free)

// ---------------- device scratch ----------------
__device__ float g_hc[N_NODES * FD];
__device__ float g_u [N_NODES * MD];
__device__ float g_v [N_NODES * MD];
__device__ float g_mi_part   [JT * N_NODES * MD];
__device__ float g_shift_part[JT * N_NODES * 24];
// fragment-major weights: per (mat, ks, wc) a 2KB chunk; within: lane*16 + nt*2 + bsel (uint32)
__device__ uint4 g_F[3 * 16 * 4 * 128];

__device__ __forceinline__ float silu_f(float v) { return v / (1.f + __expf(-v)); }

__device__ __forceinline__ void mma_fp16(float* d, uint32_t a0, uint32_t a1,
                                         uint32_t a2, uint32_t a3,
                                         uint32_t b0, uint32_t b1) {
    asm volatile("mma.sync.aligned.m16n8k16.row.col.f32.f16.f16.f32 "
                 "{%0,%1,%2,%3}, {%4,%5,%6,%7}, {%8,%9}, {%0,%1,%2,%3};\n"
                 : "+f"(d[0]), "+f"(d[1]), "+f"(d[2]), "+f"(d[3])
                 : "r"(a0), "r"(a1), "r"(a2), "r"(a3), "r"(b0), "r"(b1));
}

// ---------------- smem layout (byte offsets, 128-aligned) ----------------
#define SA_OFF    0        // 33792 : A/C tile [64][264] half
#define AUX_OFF   33792    // 8192  : We0 rows 0..7 fp32, later Wxo fp32
#define SQN_OFF   41984    // 2048  : sqn [64][8] fp32
#define XSJ_OFF   44032    // 6144  : x_j [64][24]
#define XSI_OFF   50176    // 128   : x_i [24]
#define WINF_OFF  50304    // 1024
#define RED_OFF   51328    // 256   : gate partials [64]
#define ES_OFF    51584    // 256   : e [64]
#define PXP_OFF   51840    // 8192  : px partials [4][64][8]
#define EDGE_SMEM_BYTES (60032 + 128)

// ---------------- K0: pack weights into fragment-major layout ----------------
// F[mat][ks][wc][lane*16 + nt*2 + bsel] = half2(W[kk][n], W[kk+1][n])
// n = wc*64 + nt*8 + (lane>>2), kk = ks*16 + bsel*8 + 2*(lane&3)
__global__ void prep_kernel(const float* __restrict__ We1, const float* __restrict__ Wx0,
                            const float* __restrict__ Wx1) {
    int idx = blockIdx.x * 256 + threadIdx.x;       // 98304 jobs
    int mat = idx >> 15, r = idx & 32767;
    int ks = r >> 11, r2 = r & 2047;
    int wc = r2 >> 9, r3 = r2 & 511;
    int lane = r3 >> 4, j = r3 & 15;
    int nt = j >> 1, bsel = j & 1;
    int g = lane >> 2, t4 = lane & 3;
    int n = wc * 64 + nt * 8 + g;
    int kk = ks * 16 + bsel * 8 + 2 * t4;
    const float* W = (mat == 0) ? We1 : (mat == 1) ? Wx0 : Wx1;
    __half2 v = __floats2half2_rn(W[kk * 256 + n], W[(kk + 1) * 256 + n]);
    ((uint32_t*)g_F)[idx] = *(uint32_t*)&v;
}

// ---------------- K1: hc ----------------
__global__ void hc_kernel(const float* __restrict__ x, const float* __restrict__ h) {
    int n = blockIdx.x, t = threadIdx.x;
    __shared__ float xi[24];
    if (t < 24) xi[t] = x[n * 24 + t];
    __syncthreads();
    if (t < HD) {
        g_hc[n * FD + t] = h[n * HD + t];
    } else if (t < FD) {
        int p = t - HD; int a = p >> 3, b = p & 7;
        float s = 0.f;
#pragma unroll
        for (int d = 0; d < 3; d++) { float dd = xi[a*3+d] - xi[b*3+d]; s += dd * dd; }
        g_hc[n * FD + t] = s;
    }
}

// ---------------- K2: u, v ----------------
__global__ void uv_kernel(const float* __restrict__ We0, const float* __restrict__ be0) {
    int n = blockIdx.x, t = threadIdx.x;
    __shared__ float hcs[FD];
    if (t < FD) hcs[t] = g_hc[n * FD + t];
    __syncthreads();
    float su = 0.f, sv = 0.f;
#pragma unroll 4
    for (int k = 0; k < FD; k++) {
        float hv = hcs[k];
        su += hv * We0[(8   + k) * MD + t];
        sv += hv * We0[(200 + k) * MD + t];
    }
    g_u[n * MD + t] = su;
    g_v[n * MD + t] = sv + be0[t];
}

// ---------------- fp16 GEMM, B-frags streamed from global with prefetch ----------------
// 8 warps: wr = w&1 (rows wr*32), wc = w>>1 (cols wc*64). acc = sA[64x256] @ W
__device__ __forceinline__ void gemm_gB(const uint32_t* __restrict__ sA32,
                                        const uint4* __restrict__ Fw,   // + wc*128 + lane*4
                                        float acc[2][8][4], int wr, int g, int t4) {
#pragma unroll
    for (int mt = 0; mt < 2; mt++)
#pragma unroll
        for (int nt = 0; nt < 8; nt++)
#pragma unroll
            for (int e = 0; e < 4; e++) acc[mt][nt][e] = 0.f;

    uint4 bn0 = Fw[0], bn1 = Fw[1], bn2 = Fw[2], bn3 = Fw[3];
#pragma unroll
    for (int ks = 0; ks < 16; ks++) {
        uint4 c0 = bn0, c1 = bn1, c2 = bn2, c3 = bn3;
        if (ks < 15) {
            const uint4* p = Fw + (ks + 1) * 512;   // next ks chunk (4 wc * 128 uint4)
            bn0 = p[0]; bn1 = p[1]; bn2 = p[2]; bn3 = p[3];
        }
        uint32_t bv[16] = { c0.x, c0.y, c0.z, c0.w, c1.x, c1.y, c1.z, c1.w,
                            c2.x, c2.y, c2.z, c2.w, c3.x, c3.y, c3.z, c3.w };
#pragma unroll
        for (int mt = 0; mt < 2; mt++) {
            int row = wr * 32 + mt * 16 + g;
            const uint32_t* ap0 = sA32 + row * 132 + ks * 8 + t4;
            const uint32_t* ap1 = ap0 + 8 * 132;
            uint32_t a0 = ap0[0], a2 = ap0[4];
            uint32_t a1 = ap1[0], a3 = ap1[4];
#pragma unroll
            for (int nt = 0; nt < 8; nt++)
                mma_fp16(acc[mt][nt], a0, a1, a2, a3, bv[2 * nt], bv[2 * nt + 1]);
        }
    }
}

// ---------------- K3: fused edge pipeline (M=64, 256 threads, 2 CTAs/SM) ----------------
__global__ __launch_bounds__(256, 2)
void edge_kernel(const float* __restrict__ x,
                 const float* __restrict__ We0,
                 const float* __restrict__ be1,
                 const float* __restrict__ Winf, const float* __restrict__ binf,
                 const float* __restrict__ bx0, const float* __restrict__ bx1,
                 const float* __restrict__ Wxo, const float* __restrict__ bxo) {
    extern __shared__ __align__(128) char smem[];
    __half* sA    = (__half*)(smem + SA_OFF);
    uint32_t* sA32 = (uint32_t*)(smem + SA_OFF);
    float* sAux  = (float*)(smem + AUX_OFF);
    float* sqn_s = (float*)(smem + SQN_OFF);
    float* xs_j  = (float*)(smem + XSJ_OFF);
    float* xs_i  = (float*)(smem + XSI_OFF);
    float* sWinf = (float*)(smem + WINF_OFF);
    float* red   = (float*)(smem + RED_OFF);
    float* e_s   = (float*)(smem + ES_OFF);
    float* pxp   = (float*)(smem + PXP_OFF);

    int tid = threadIdx.x;
    int lane = tid & 31, w = tid >> 5;
    int wr = w & 1, wc = w >> 1;
    int g = lane >> 2, t4 = lane & 3;
    int jt = blockIdx.x, i = blockIdx.y;
    int j0 = jt * TJ;

    const uint4* Fbase = g_F + (size_t)wc * 128 + lane * 4;

    // --- prologue: constants + geometry ---
    if (tid < 256) sWinf[tid] = Winf[tid];
    for (int q = tid; q < 8 * MD; q += 256) sAux[q] = We0[q];
    if (tid < 24) xs_i[tid] = x[i * 24 + tid];
    for (int q = tid; q < TJ * 24; q += 256) xs_j[q] = x[j0 * 24 + q];
    if (tid < 64) red[tid] = 0.f;
    __syncthreads();

    for (int q = tid; q < TJ * 8; q += 256) {
        int jl = q >> 3, hh = q & 7;
        float s = 0.f;
#pragma unroll
        for (int d = 0; d < 3; d++) {
            float dd = xs_j[jl*24 + hh*3 + d] - xs_i[hh*3 + d];
            s += dd * dd;
        }
        sqn_s[q] = s;
    }
    __syncthreads();

    // --- A1 = half(silu(sqn @ We0[0:8] + u[j] + v[i])) ---
    {
        int c = tid;
        float vv = g_v[i * MD + c];
        float w8[8];
#pragma unroll
        for (int t8 = 0; t8 < 8; t8++) w8[t8] = sAux[t8 * 256 + c];
        for (int jl = 0; jl < TJ; jl++) {
            float a = vv + g_u[(j0 + jl) * MD + c];
#pragma unroll
            for (int t8 = 0; t8 < 8; t8++) a += sqn_s[jl * 8 + t8] * w8[t8];
            sA[jl * SA_STRH + c] = __float2half_rn(silu_f(a));
        }
    }
    __syncthreads();

    float acc[2][8][4];

    // ================= GEMM1: m = silu(A1 @ We1 + be1), masked =================
    gemm_gB(sA32, Fbase, acc, wr, g, t4);
    __syncthreads();                      // all A reads done before epilogue writes
    {
#pragma unroll
        for (int mt = 0; mt < 2; mt++) {
            int r0 = wr * 32 + mt * 16 + g, r1 = r0 + 8;
            bool s0 = (j0 + r0) == i;
            bool s1 = (j0 + r1) == i;
            float gp0 = 0.f, gp1 = 0.f;
#pragma unroll
            for (int nt = 0; nt < 8; nt++) {
                int cn = wc * 64 + nt * 8 + 2 * t4;
                float w0 = sWinf[cn], w1 = sWinf[cn + 1];
                float b0v = be1[cn], b1v = be1[cn + 1];
                float v0 = s0 ? 0.f : silu_f(acc[mt][nt][0] + b0v);
                float v1 = s0 ? 0.f : silu_f(acc[mt][nt][1] + b1v);
                float v2 = s1 ? 0.f : silu_f(acc[mt][nt][2] + b0v);
                float v3 = s1 ? 0.f : silu_f(acc[mt][nt][3] + b1v);
                *(__half2*)&sA[r0 * SA_STRH + cn] = __floats2half2_rn(v0, v1);
                *(__half2*)&sA[r1 * SA_STRH + cn] = __floats2half2_rn(v2, v3);
                gp0 += v0 * w0 + v1 * w1;
                gp1 += v2 * w0 + v3 * w1;
            }
            gp0 += __shfl_xor_sync(0xffffffff, gp0, 1);
            gp0 += __shfl_xor_sync(0xffffffff, gp0, 2);
            gp1 += __shfl_xor_sync(0xffffffff, gp1, 1);
            gp1 += __shfl_xor_sync(0xffffffff, gp1, 2);
            if (t4 == 0) { atomicAdd(&red[r0], gp0); atomicAdd(&red[r1], gp1); }
        }
    }
    __syncthreads();

    // --- gate e ---
    if (tid < 64) {
        float s = red[tid] + binf[0];
        e_s[tid] = (j0 + tid == i) ? 0.f : 1.f / (1.f + __expf(-s));
    }
    __syncthreads();

    // --- m_i partials (reads only; GEMM2 may follow without extra barrier) ---
    {
        int c = tid;
        float a = 0.f;
#pragma unroll 4
        for (int rr = 0; rr < TJ; rr++)
            a += __half2float(sA[rr * SA_STRH + c]) * e_s[rr];
        g_mi_part[(jt * N_NODES + i) * MD + c] = a;
    }

    // ================= GEMM2: s1 = silu(m @ Wx0 + bx0) =================
    gemm_gB(sA32, Fbase + 8192, acc, wr, g, t4);
    __syncthreads();
#pragma unroll
    for (int mt = 0; mt < 2; mt++) {
        int r0 = wr * 32 + mt * 16 + g, r1 = r0 + 8;
#pragma unroll
        for (int nt = 0; nt < 8; nt++) {
            int cn = wc * 64 + nt * 8 + 2 * t4;
            float b0v = bx0[cn], b1v = bx0[cn + 1];
            *(__half2*)&sA[r0 * SA_STRH + cn] =
                __floats2half2_rn(silu_f(acc[mt][nt][0] + b0v), silu_f(acc[mt][nt][1] + b1v));
            *(__half2*)&sA[r1 * SA_STRH + cn] =
                __floats2half2_rn(silu_f(acc[mt][nt][2] + b0v), silu_f(acc[mt][nt][3] + b1v));
        }
    }
    __syncthreads();

    // ================= GEMM3: s2 = silu(s1 @ Wx1 + bx1) =================
    gemm_gB(sA32, Fbase + 16384, acc, wr, g, t4);
    __syncthreads();
#pragma unroll
    for (int mt = 0; mt < 2; mt++) {
        int r0 = wr * 32 + mt * 16 + g, r1 = r0 + 8;
#pragma unroll
        for (int nt = 0; nt < 8; nt++) {
            int cn = wc * 64 + nt * 8 + 2 * t4;
            float b0v = bx1[cn], b1v = bx1[cn + 1];
            *(__half2*)&sA[r0 * SA_STRH + cn] =
                __floats2half2_rn(silu_f(acc[mt][nt][0] + b0v), silu_f(acc[mt][nt][1] + b1v));
            *(__half2*)&sA[r1 * SA_STRH + cn] =
                __floats2half2_rn(silu_f(acc[mt][nt][2] + b0v), silu_f(acc[mt][nt][3] + b1v));
        }
    }
    for (int q = tid; q < 2048; q += 256) sAux[q] = Wxo[q];   // Wxo after A1 is done with We0
    __syncthreads();

    // --- px partials: px[r] = s2[r] @ Wxo ---
    {
        int r = tid & 63, chunk = tid >> 6;
        float pa[8];
#pragma unroll
        for (int hh = 0; hh < 8; hh++) pa[hh] = 0.f;
        int c0 = chunk * 64;
        for (int c = c0; c < c0 + 64; c++) {
            float v = __half2float(sA[r * SA_STRH + c]);
#pragma unroll
            for (int hh = 0; hh < 8; hh++) pa[hh] += v * sAux[c * 8 + hh];
        }
#pragma unroll
        for (int hh = 0; hh < 8; hh++) pxp[(chunk * 64 + r) * 8 + hh] = pa[hh];
    }
    __syncthreads();
    if (tid < 64) {
#pragma unroll
        for (int hh = 0; hh < 8; hh++)
            pxp[tid * 8 + hh] = pxp[tid * 8 + hh] + pxp[(64 + tid) * 8 + hh]
                              + pxp[(128 + tid) * 8 + hh] + pxp[(192 + tid) * 8 + hh] + bxo[hh];
    }
    __syncthreads();

    // --- shift partials ---
    if (tid < 24) {
        int hh = tid / 3, d = tid % 3;
        float accs = 0.f;
        for (int jl = 0; jl < TJ; jl++) {
            float dn  = xs_j[jl*24 + hh*3 + d] - xs_i[hh*3 + d];
            float nrm = sqrtf(sqn_s[jl*8 + hh] + 1e-8f) + 1.0f;
            accs += (dn / nrm) * pxp[jl * 8 + hh];
        }
        g_shift_part[(jt * N_NODES + i) * 24 + tid] = accs;
    }
}

// ---------------- K4: phi_h per node ----------------
__global__ void hnode_kernel(const float* __restrict__ h,
                             const float* __restrict__ Wh0, const float* __restrict__ bh0,
                             const float* __restrict__ Wh1, const float* __restrict__ bh1,
                             const float* __restrict__ Who, const float* __restrict__ bho,
                             float* __restrict__ out) {
    int n = blockIdx.x, t = threadIdx.x;
    __shared__ float sin_s[384];
    __shared__ float s1[256];
    __shared__ float s2[256];
    float mi = 0.f;
#pragma unroll
    for (int p = 0; p < JT; p++) mi += g_mi_part[(p * N_NODES + n) * MD + t];
    sin_s[t] = mi;
    if (t < HD) sin_s[256 + t] = h[n * HD + t];
    __syncthreads();
    {
        float a0=0,a1=0,a2=0,a3=0;
        for (int k = 0; k < 384; k += 4) {
            a0 += sin_s[k  ] * Wh0[(k  ) * 256 + t];
            a1 += sin_s[k+1] * Wh0[(k+1) * 256 + t];
            a2 += sin_s[k+2] * Wh0[(k+2) * 256 + t];
            a3 += sin_s[k+3] * Wh0[(k+3) * 256 + t];
        }
        s1[t] = silu_f(a0 + a1 + a2 + a3 + bh0[t]);
    }
    __syncthreads();
    {
        float a0=0,a1=0,a2=0,a3=0;
        for (int k = 0; k < 256; k += 4) {
            a0 += s1[k  ] * Wh1[(k  ) * 256 + t];
            a1 += s1[k+1] * Wh1[(k+1) * 256 + t];
            a2 += s1[k+2] * Wh1[(k+2) * 256 + t];
            a3 += s1[k+3] * Wh1[(k+3) * 256 + t];
        }
        s2[t] = silu_f(a0 + a1 + a2 + a3 + bh1[t]);
    }
    __syncthreads();
    if (t < HD) {
        float a0=0,a1=0,a2=0,a3=0;
        for (int k = 0; k < 256; k += 4) {
            a0 += s2[k  ] * Who[(k  ) * 128 + t];
            a1 += s2[k+1] * Who[(k+1) * 128 + t];
            a2 += s2[k+2] * Who[(k+2) * 128 + t];
            a3 += s2[k+3] * Who[(k+3) * 128 + t];
        }
        out[12288 + n * HD + t] = h[n * HD + t] + a0 + a1 + a2 + a3 + bho[t];
    }
}

// ---------------- K5: x_new ----------------
__global__ void xout_kernel(const float* __restrict__ x, float* __restrict__ out) {
    int idx = blockIdx.x * blockDim.x + threadIdx.x;
    if (idx < N_NODES * 24) {
        float s = 0.f;
#pragma unroll
        for (int p = 0; p < JT; p++) s += g_shift_part[p * N_NODES * 24 + idx];
        out[idx] = x[idx] + s / (float)(N_NODES - 1);
    }
}

// ---------------- launch ----------------
extern "C" void kernel_launch(void* const* d_in, const int* in_sizes, int n_in,
                              void* d_out, int out_size) {
    const float* x    = (const float*)d_in[0];
    const float* h    = (const float*)d_in[1];
    const float* We0  = (const float*)d_in[2];
    const float* be0  = (const float*)d_in[3];
    const float* We1  = (const float*)d_in[4];
    const float* be1  = (const float*)d_in[5];
    const float* Winf = (const float*)d_in[6];
    const float* binf = (const float*)d_in[7];
    const float* Wx0  = (const float*)d_in[8];
    const float* bx0  = (const float*)d_in[9];
    const float* Wx1  = (const float*)d_in[10];
    const float* bx1  = (const float*)d_in[11];
    const float* Wxo  = (const float*)d_in[12];
    const float* bxo  = (const float*)d_in[13];
    const float* Wh0  = (const float*)d_in[14];
    const float* bh0  = (const float*)d_in[15];
    const float* Wh1  = (const float*)d_in[16];
    const float* bh1  = (const float*)d_in[17];
    const float* Who  = (const float*)d_in[18];
    const float* bho  = (const float*)d_in[19];
    float* out = (float*)d_out;

    cudaFuncSetAttribute(edge_kernel, cudaFuncAttributeMaxDynamicSharedMemorySize,
                         EDGE_SMEM_BYTES);

    prep_kernel<<<384, 256>>>(We1, Wx0, Wx1);
    hc_kernel<<<N_NODES, 256>>>(x, h);
    uv_kernel<<<N_NODES, 256>>>(We0, be0);
    edge_kernel<<<dim3(JT, N_NODES), 256, EDGE_SMEM_BYTES>>>(
        x, We0, be1, Winf, binf, bx0, bx1, Wxo, bxo);
    hnode_kernel<<<N_NODES, 256>>>(h, Wh0, bh0, Wh1, bh1, Who, bho, out);
    xout_kernel<<<48, 256>>>(x, out);
}

// round 17
// speedup vs baseline: 1.0286x; 1.0286x over previous
#include <cuda_runtime.h>
#include <cuda_fp16.h>
#include <cstdint>

#define N_NODES 512
#define HD      128
#define FD      192
#define MD      256
#define JT      8
#define TJ      64
#define SA_STRH 264      // sA row stride in halves (132 words == 4 mod 32 -> conflict-free)
#define STG_STRH 40      // stage row stride in halves (80 B, 16B-aligned; 20 words -> conflict-free)

// ---------------- device scratch ----------------
__device__ float g_hc[N_NODES * FD];
__device__ float g_u [N_NODES * MD];
__device__ float g_v [N_NODES * MD];
__device__ float g_mi_part   [JT * N_NODES * MD];
__device__ float g_shift_part[JT * N_NODES * 24];
__device__ __half g_We1h[MD * MD];   // Wt[n][k] = half(W[k][n])
__device__ __half g_Wx0h[MD * MD];
__device__ __half g_Wx1h[MD * MD];

__device__ __forceinline__ float silu_f(float v) { return v / (1.f + __expf(-v)); }

__device__ __forceinline__ uint32_t smem_u32(const void* p) {
    uint32_t a;
    asm("{ .reg .u64 t; cvta.to.shared.u64 t, %1; cvt.u32.u64 %0, t; }" : "=r"(a) : "l"(p));
    return a;
}

__device__ __forceinline__ void mma_fp16(float* d, uint32_t a0, uint32_t a1,
                                         uint32_t a2, uint32_t a3,
                                         uint32_t b0, uint32_t b1) {
    asm volatile("mma.sync.aligned.m16n8k16.row.col.f32.f16.f16.f32 "
                 "{%0,%1,%2,%3}, {%4,%5,%6,%7}, {%8,%9}, {%0,%1,%2,%3};\n"
                 : "+f"(d[0]), "+f"(d[1]), "+f"(d[2]), "+f"(d[3])
                 : "r"(a0), "r"(a1), "r"(a2), "r"(a3), "r"(b0), "r"(b1));
}

#define BARG(id) asm volatile("bar.sync %0, 256;" :: "r"(id) : "memory")

// ---------------- smem layout (byte offsets, 128-aligned) ----------------
#define SA_OFF    0        // 67584 : A/C tile [128][264] half (group g: rows g*64..)
#define STG_OFF   67584    // 81920 : 4 stage bufs [256][40] half (2 per group)
#define WE0_OFF   149504   // 8192  : We0 rows 0..7 fp32 (read-only)
#define WXO_OFF   157696   // 8192  : Wxo fp32 (read-only)
#define SQN_OFF   165888   // 4096  : sqn [2][64][8] fp32
#define XSJ_OFF   169984   // 6144  : x_j [64][24]
#define XSI_OFF   176128   // 192   : x_i [2][24]
#define WINF_OFF  176320   // 1024
#define RED_OFF   177344   // 512   : gate partials [2][64]
#define ES_OFF    177856   // 512   : e [2][64]
#define PXP_OFF   178368   // 16384 : px partials [2][4][64][8]
#define EDGE_SMEM_BYTES (194752 + 128)
#define STG_BYTES 20480

// ---------------- K0: transpose + halve weights ----------------
__global__ void prep_kernel(const float* __restrict__ We1, const float* __restrict__ Wx0,
                            const float* __restrict__ Wx1) {
    __shared__ float t[32][33];
    int b = blockIdx.x;            // 192 blocks
    int mat = b >> 6, tile = b & 63;
    int tk = tile >> 3, tn = tile & 7;
    const float* S = (mat == 0) ? We1 : (mat == 1) ? Wx0 : Wx1;
    __half* D = (mat == 0) ? g_We1h : (mat == 1) ? g_Wx0h : g_Wx1h;
    int r0 = threadIdx.x >> 5, c = threadIdx.x & 31;
#pragma unroll
    for (int q = 0; q < 4; q++) {
        int r = r0 + q * 8;
        t[r][c] = S[(tk * 32 + r) * 256 + tn * 32 + c];
    }
    __syncthreads();
#pragma unroll
    for (int q = 0; q < 4; q++) {
        int r = r0 + q * 8;
        D[(tn * 32 + r) * 256 + tk * 32 + c] = __float2half_rn(t[c][r]);
    }
}

// ---------------- K1: hc ----------------
__global__ void hc_kernel(const float* __restrict__ x, const float* __restrict__ h) {
    int n = blockIdx.x, t = threadIdx.x;
    __shared__ float xi[24];
    if (t < 24) xi[t] = x[n * 24 + t];
    __syncthreads();
    if (t < HD) {
        g_hc[n * FD + t] = h[n * HD + t];
    } else if (t < FD) {
        int p = t - HD; int a = p >> 3, b = p & 7;
        float s = 0.f;
#pragma unroll
        for (int d = 0; d < 3; d++) { float dd = xi[a*3+d] - xi[b*3+d]; s += dd * dd; }
        g_hc[n * FD + t] = s;
    }
}

// ---------------- K2: u, v ----------------
__global__ void uv_kernel(const float* __restrict__ We0, const float* __restrict__ be0) {
    int n = blockIdx.x, t = threadIdx.x;
    __shared__ float hcs[FD];
    if (t < FD) hcs[t] = g_hc[n * FD + t];
    __syncthreads();
    float su = 0.f, sv = 0.f;
#pragma unroll 4
    for (int k = 0; k < FD; k++) {
        float hv = hcs[k];
        su += hv * We0[(8   + k) * MD + t];
        sv += hv * We0[(200 + k) * MD + t];
    }
    g_u[n * MD + t] = su;
    g_v[n * MD + t] = sv + be0[t];
}

// ---------------- group-local weight staging: 32 k-halves for 256 n ----------------
__device__ __forceinline__ void stage_cp(const __half* __restrict__ Wt, int kc,
                                         uint32_t dst, int gtid) {
#pragma unroll
    for (int p = 0; p < 4; p++) {
        int s = gtid + p * 256;                // 1024 jobs of 16B
        int n = s >> 2, q = s & 3;
        const __half* src = Wt + n * 256 + kc * 32 + q * 8;
        uint32_t d = dst + (uint32_t)(n * (STG_STRH * 2) + q * 16);
        asm volatile("cp.async.cg.shared.global [%0], [%1], 16;" :: "r"(d), "l"(src));
    }
    asm volatile("cp.async.commit_group;" ::: "memory");
}

// ---------------- group-local staged GEMM: acc = sA[rows rowbase..+63] @ Wt ----------------
// 8 warps/group: wr = wg&1 (rows wr*32), wc = wg>>1 (cols wc*64)
// PRECONDITION: stage 0 already issued into bufA.
__device__ __forceinline__ void gemm_grp(const uint32_t* __restrict__ sA32, int rowbase,
                                         const __half* __restrict__ Wt,
                                         uint32_t bufA_a, uint32_t bufB_a,
                                         const __half* __restrict__ bufA_p,
                                         const __half* __restrict__ bufB_p,
                                         float acc[2][8][4], int gtid,
                                         int wr, int wc, int g, int t4, int barid) {
#pragma unroll
    for (int mt = 0; mt < 2; mt++)
#pragma unroll
        for (int nt = 0; nt < 8; nt++)
#pragma unroll
            for (int e = 0; e < 4; e++) acc[mt][nt][e] = 0.f;

#pragma unroll 1
    for (int s = 0; s < 8; s++) {
        if (s < 7) {
            stage_cp(Wt, s + 1, (s & 1) ? bufA_a : bufB_a, gtid);
            asm volatile("cp.async.wait_group 1;" ::: "memory");
        } else {
            asm volatile("cp.async.wait_group 0;" ::: "memory");
        }
        BARG(barid);
        const __half* stg = (s & 1) ? bufB_p : bufA_p;
#pragma unroll
        for (int sub = 0; sub < 2; sub++) {
            uint32_t b0[8], b1[8];
#pragma unroll
            for (int nt = 0; nt < 8; nt++) {
                const uint32_t* bp = (const uint32_t*)(stg + (wc * 64 + nt * 8 + g) * STG_STRH)
                                     + sub * 8 + t4;
                b0[nt] = bp[0];
                b1[nt] = bp[4];
            }
#pragma unroll
            for (int mt = 0; mt < 2; mt++) {
                int row = rowbase + wr * 32 + mt * 16 + g;
                const uint32_t* ap0 = sA32 + row * 132 + s * 16 + sub * 8 + t4;
                const uint32_t* ap1 = ap0 + 8 * 132;
                uint32_t a0 = ap0[0], a2 = ap0[4];
                uint32_t a1 = ap1[0], a3 = ap1[4];
#pragma unroll
                for (int nt = 0; nt < 8; nt++)
                    mma_fp16(acc[mt][nt], a0, a1, a2, a3, b0[nt], b1[nt]);
            }
        }
        BARG(barid);
    }
}

// ---------------- K3: fused edge pipeline, two independent 256-thr groups ----------------
__global__ __launch_bounds__(512, 1)
void edge_kernel(const float* __restrict__ x,
                 const float* __restrict__ We0,
                 const float* __restrict__ be1,
                 const float* __restrict__ Winf, const float* __restrict__ binf,
                 const float* __restrict__ bx0, const float* __restrict__ bx1,
                 const float* __restrict__ Wxo, const float* __restrict__ bxo) {
    extern __shared__ __align__(128) char smem[];
    __half* sA     = (__half*)(smem + SA_OFF);
    uint32_t* sA32 = (uint32_t*)(smem + SA_OFF);
    float* sWe0  = (float*)(smem + WE0_OFF);
    float* sWxo  = (float*)(smem + WXO_OFF);
    float* sqn_s = (float*)(smem + SQN_OFF);
    float* xs_j  = (float*)(smem + XSJ_OFF);
    float* xs_i  = (float*)(smem + XSI_OFF);
    float* sWinf = (float*)(smem + WINF_OFF);
    float* red   = (float*)(smem + RED_OFF);
    float* e_s   = (float*)(smem + ES_OFF);
    float* pxp   = (float*)(smem + PXP_OFF);
    uint32_t sbase = smem_u32(smem);

    int tid = threadIdx.x;
    int lane = tid & 31;
    int gtid = tid & 255, grp = tid >> 8;
    int wg = (tid >> 5) & 7;
    int wr = wg & 1, wc = wg >> 1;
    int g = lane >> 2, t4 = lane & 3;
    int jt = blockIdx.x, ip = blockIdx.y;
    int j0 = jt * TJ;
    int i_this = ip * 2 + grp;
    int rowbase = grp * 64;
    int barid = grp + 1;

    uint32_t bufA_a = sbase + STG_OFF + (uint32_t)grp * (2 * STG_BYTES);
    uint32_t bufB_a = bufA_a + STG_BYTES;
    const __half* bufA_p = (const __half*)(smem + STG_OFF + grp * (2 * STG_BYTES));
    const __half* bufB_p = (const __half*)(smem + STG_OFF + grp * (2 * STG_BYTES) + STG_BYTES);

    // --- prologue (full block) ---
    if (tid < 256) sWinf[tid] = Winf[tid];
    for (int q = tid; q < 8 * MD; q += 512) sWe0[q] = We0[q];
    for (int q = tid; q < 2048; q += 512) sWxo[q] = Wxo[q];
    if (tid < 48) xs_i[tid] = x[(ip * 2) * 24 + tid];
    for (int q = tid; q < TJ * 24; q += 512) xs_j[q] = x[j0 * 24 + q];
    if (tid < 128) red[tid] = 0.f;
    __syncthreads();

    for (int q = tid; q < 2 * TJ * 8; q += 512) {
        int half = q >> 9, rem = q & 511, jl = rem >> 3, hh = rem & 7;
        float s = 0.f;
#pragma unroll
        for (int d = 0; d < 3; d++) {
            float dd = xs_j[jl*24 + hh*3 + d] - xs_i[half*24 + hh*3 + d];
            s += dd * dd;
        }
        sqn_s[q] = s;
    }
    __syncthreads();
    // ======== groups fully independent from here ========

    // pre-issue stage 0 of GEMM1 weights (overlaps A1 compute)
    stage_cp(g_We1h, 0, bufA_a, gtid);

    // --- A1 = half(silu(sqn @ We0[0:8] + u[j] + v[i])) for this group's 64 rows ---
    {
        int c = gtid;
        float vv = g_v[i_this * MD + c];
        float w8[8];
#pragma unroll
        for (int t8 = 0; t8 < 8; t8++) w8[t8] = sWe0[t8 * 256 + c];
        for (int jl = 0; jl < TJ; jl++) {
            float a = vv + g_u[(j0 + jl) * MD + c];
#pragma unroll
            for (int t8 = 0; t8 < 8; t8++) a += sqn_s[grp * 512 + jl * 8 + t8] * w8[t8];
            sA[(rowbase + jl) * SA_STRH + c] = __float2half_rn(silu_f(a));
        }
    }

    float acc[2][8][4];

    // ================= GEMM1: m = silu(A1 @ We1 + be1), masked =================
    gemm_grp(sA32, rowbase, g_We1h, bufA_a, bufB_a, bufA_p, bufB_p,
             acc, gtid, wr, wc, g, t4, barid);
    stage_cp(g_Wx0h, 0, bufA_a, gtid);       // pre-stage GEMM2 under epilogue

    // --- epilogue 1: write m, gate partials ---
    {
#pragma unroll
        for (int mt = 0; mt < 2; mt++) {
            int rl0 = wr * 32 + mt * 16 + g, rl1 = rl0 + 8;
            bool s0 = (j0 + rl0) == i_this;
            bool s1 = (j0 + rl1) == i_this;
            float gp0 = 0.f, gp1 = 0.f;
#pragma unroll
            for (int nt = 0; nt < 8; nt++) {
                int cn = wc * 64 + nt * 8 + 2 * t4;
                float w0 = sWinf[cn], w1 = sWinf[cn + 1];
                float b0v = be1[cn], b1v = be1[cn + 1];
                float v0 = s0 ? 0.f : silu_f(acc[mt][nt][0] + b0v);
                float v1 = s0 ? 0.f : silu_f(acc[mt][nt][1] + b1v);
                float v2 = s1 ? 0.f : silu_f(acc[mt][nt][2] + b0v);
                float v3 = s1 ? 0.f : silu_f(acc[mt][nt][3] + b1v);
                *(__half2*)&sA[(rowbase + rl0) * SA_STRH + cn] = __floats2half2_rn(v0, v1);
                *(__half2*)&sA[(rowbase + rl1) * SA_STRH + cn] = __floats2half2_rn(v2, v3);
                gp0 += v0 * w0 + v1 * w1;
                gp1 += v2 * w0 + v3 * w1;
            }
            gp0 += __shfl_xor_sync(0xffffffff, gp0, 1);
            gp0 += __shfl_xor_sync(0xffffffff, gp0, 2);
            gp1 += __shfl_xor_sync(0xffffffff, gp1, 1);
            gp1 += __shfl_xor_sync(0xffffffff, gp1, 2);
            if (t4 == 0) {
                atomicAdd(&red[grp * 64 + rl0], gp0);
                atomicAdd(&red[grp * 64 + rl1], gp1);
            }
        }
    }
    BARG(barid);

    // --- gate e ---
    if (gtid < 64) {
        float s = red[grp * 64 + gtid] + binf[0];
        e_s[grp * 64 + gtid] = (j0 + gtid == i_this) ? 0.f : 1.f / (1.f + __expf(-s));
    }
    BARG(barid);

    // --- m_i ---
    {
        int c = gtid;
        float a = 0.f;
#pragma unroll 4
        for (int rr = 0; rr < TJ; rr++)
            a += __half2float(sA[(rowbase + rr) * SA_STRH + c]) * e_s[grp * 64 + rr];
        g_mi_part[(jt * N_NODES + i_this) * MD + c] = a;
    }

    // ================= GEMM2: s1 = silu(m @ Wx0 + bx0) =================
    gemm_grp(sA32, rowbase, g_Wx0h, bufA_a, bufB_a, bufA_p, bufB_p,
             acc, gtid, wr, wc, g, t4, barid);
    stage_cp(g_Wx1h, 0, bufA_a, gtid);       // pre-stage GEMM3 under epilogue
#pragma unroll
    for (int mt = 0; mt < 2; mt++) {
        int rl0 = wr * 32 + mt * 16 + g, rl1 = rl0 + 8;
#pragma unroll
        for (int nt = 0; nt < 8; nt++) {
            int cn = wc * 64 + nt * 8 + 2 * t4;
            float b0v = bx0[cn], b1v = bx0[cn + 1];
            *(__half2*)&sA[(rowbase + rl0) * SA_STRH + cn] =
                __floats2half2_rn(silu_f(acc[mt][nt][0] + b0v), silu_f(acc[mt][nt][1] + b1v));
            *(__half2*)&sA[(rowbase + rl1) * SA_STRH + cn] =
                __floats2half2_rn(silu_f(acc[mt][nt][2] + b0v), silu_f(acc[mt][nt][3] + b1v));
        }
    }

    // ================= GEMM3: s2 = silu(s1 @ Wx1 + bx1) =================
    // (its first internal barrier orders epilogue-2 writes before MMA reads)
    gemm_grp(sA32, rowbase, g_Wx1h, bufA_a, bufB_a, bufA_p, bufB_p,
             acc, gtid, wr, wc, g, t4, barid);
#pragma unroll
    for (int mt = 0; mt < 2; mt++) {
        int rl0 = wr * 32 + mt * 16 + g, rl1 = rl0 + 8;
#pragma unroll
        for (int nt = 0; nt < 8; nt++) {
            int cn = wc * 64 + nt * 8 + 2 * t4;
            float b0v = bx1[cn], b1v = bx1[cn + 1];
            *(__half2*)&sA[(rowbase + rl0) * SA_STRH + cn] =
                __floats2half2_rn(silu_f(acc[mt][nt][0] + b0v), silu_f(acc[mt][nt][1] + b1v));
            *(__half2*)&sA[(rowbase + rl1) * SA_STRH + cn] =
                __floats2half2_rn(silu_f(acc[mt][nt][2] + b0v), silu_f(acc[mt][nt][3] + b1v));
        }
    }
    BARG(barid);

    // --- px partials: px[r] = s2[r] @ Wxo (4 column chunks per group) ---
    {
        int r = gtid & 63, chunk = gtid >> 6;
        float pa[8];
#pragma unroll
        for (int hh = 0; hh < 8; hh++) pa[hh] = 0.f;
        int c0 = chunk * 64;
        for (int c = c0; c < c0 + 64; c++) {
            float v = __half2float(sA[(rowbase + r) * SA_STRH + c]);
#pragma unroll
            for (int hh = 0; hh < 8; hh++) pa[hh] += v * sWxo[c * 8 + hh];
        }
#pragma unroll
        for (int hh = 0; hh < 8; hh++)
            pxp[((grp * 4 + chunk) * 64 + r) * 8 + hh] = pa[hh];
    }
    BARG(barid);
    if (gtid < 64) {
        int base = grp * 4 * 64;
#pragma unroll
        for (int hh = 0; hh < 8; hh++)
            pxp[(base + gtid) * 8 + hh] =
                pxp[(base + gtid) * 8 + hh] + pxp[(base + 64 + gtid) * 8 + hh]
              + pxp[(base + 128 + gtid) * 8 + hh] + pxp[(base + 192 + gtid) * 8 + hh] + bxo[hh];
    }
    BARG(barid);

    // --- shift partials ---
    if (gtid < 24) {
        int hh = gtid / 3, d = gtid % 3;
        float accs = 0.f;
        for (int jl = 0; jl < TJ; jl++) {
            float dn  = xs_j[jl*24 + hh*3 + d] - xs_i[grp*24 + hh*3 + d];
            float nrm = sqrtf(sqn_s[grp*512 + jl*8 + hh] + 1e-8f) + 1.0f;
            accs += (dn / nrm) * pxp[(grp * 4 * 64 + jl) * 8 + hh];
        }
        g_shift_part[(jt * N_NODES + i_this) * 24 + gtid] = accs;
    }
}

// ---------------- K4: phi_h per node ----------------
__global__ void hnode_kernel(const float* __restrict__ h,
                             const float* __restrict__ Wh0, const float* __restrict__ bh0,
                             const float* __restrict__ Wh1, const float* __restrict__ bh1,
                             const float* __restrict__ Who, const float* __restrict__ bho,
                             float* __restrict__ out) {
    int n = blockIdx.x, t = threadIdx.x;
    __shared__ float sin_s[384];
    __shared__ float s1[256];
    __shared__ float s2[256];
    float mi = 0.f;
#pragma unroll
    for (int p = 0; p < JT; p++) mi += g_mi_part[(p * N_NODES + n) * MD + t];
    sin_s[t] = mi;
    if (t < HD) sin_s[256 + t] = h[n * HD + t];
    __syncthreads();
    {
        float a0=0,a1=0,a2=0,a3=0;
        for (int k = 0; k < 384; k += 4) {
            a0 += sin_s[k  ] * Wh0[(k  ) * 256 + t];
            a1 += sin_s[k+1] * Wh0[(k+1) * 256 + t];
            a2 += sin_s[k+2] * Wh0[(k+2) * 256 + t];
            a3 += sin_s[k+3] * Wh0[(k+3) * 256 + t];
        }
        s1[t] = silu_f(a0 + a1 + a2 + a3 + bh0[t]);
    }
    __syncthreads();
    {
        float a0=0,a1=0,a2=0,a3=0;
        for (int k = 0; k < 256; k += 4) {
            a0 += s1[k  ] * Wh1[(k  ) * 256 + t];
            a1 += s1[k+1] * Wh1[(k+1) * 256 + t];
            a2 += s1[k+2] * Wh1[(k+2) * 256 + t];
            a3 += s1[k+3] * Wh1[(k+3) * 256 + t];
        }
        s2[t] = silu_f(a0 + a1 + a2 + a3 + bh1[t]);
    }
    __syncthreads();
    if (t < HD) {
        float a0=0,a1=0,a2=0,a3=0;
        for (int k = 0; k < 256; k += 4) {
            a0 += s2[k  ] * Who[(k  ) * 128 + t];
            a1 += s2[k+1] * Who[(k+1) * 128 + t];
            a2 += s2[k+2] * Who[(k+2) * 128 + t];
            a3 += s2[k+3] * Who[(k+3) * 128 + t];
        }
        out[12288 + n * HD + t] = h[n * HD + t] + a0 + a1 + a2 + a3 + bho[t];
    }
}

// ---------------- K5: x_new ----------------
__global__ void xout_kernel(const float* __restrict__ x, float* __restrict__ out) {
    int idx = blockIdx.x * blockDim.x + threadIdx.x;
    if (idx < N_NODES * 24) {
        float s = 0.f;
#pragma unroll
        for (int p = 0; p < JT; p++) s += g_shift_part[p * N_NODES * 24 + idx];
        out[idx] = x[idx] + s / (float)(N_NODES - 1);
    }
}

// ---------------- launch ----------------
extern "C" void kernel_launch(void* const* d_in, const int* in_sizes, int n_in,
                              void* d_out, int out_size) {
    const float* x    = (const float*)d_in[0];
    const float* h    = (const float*)d_in[1];
    const float* We0  = (const float*)d_in[2];
    const float* be0  = (const float*)d_in[3];
    const float* We1  = (const float*)d_in[4];
    const float* be1  = (const float*)d_in[5];
    const float* Winf = (const float*)d_in[6];
    const float* binf = (const float*)d_in[7];
    const float* Wx0  = (const float*)d_in[8];
    const float* bx0  = (const float*)d_in[9];
    const float* Wx1  = (const float*)d_in[10];
    const float* bx1  = (const float*)d_in[11];
    const float* Wxo  = (const float*)d_in[12];
    const float* bxo  = (const float*)d_in[13];
    const float* Wh0  = (const float*)d_in[14];
    const float* bh0  = (const float*)d_in[15];
    const float* Wh1  = (const float*)d_in[16];
    const float* bh1  = (const float*)d_in[17];
    const float* Who  = (const float*)d_in[18];
    const float* bho  = (const float*)d_in[19];
    float* out = (float*)d_out;

    cudaFuncSetAttribute(edge_kernel, cudaFuncAttributeMaxDynamicSharedMemorySize,
                         EDGE_SMEM_BYTES);

    prep_kernel<<<192, 256>>>(We1, Wx0, Wx1);
    hc_kernel<<<N_NODES, 256>>>(x, h);
    uv_kernel<<<N_NODES, 256>>>(We0, be0);
    edge_kernel<<<dim3(JT, N_NODES / 2), 512, EDGE_SMEM_BYTES>>>(
        x, We0, be1, Winf, binf, bx0, bx1, Wxo, bxo);
    hnode_kernel<<<N_NODES, 256>>>(h, Wh0, bh0, Wh1, bh1, Who, bho, out);
    xout_kernel<<<48, 256>>>(x, out);
}